// round 4
// baseline (speedup 1.0000x reference)
#include <cuda_runtime.h>
#include <math.h>

#define NBLK 128
#define NTHR 256
#define HID  128
#define BINS 513
#define WIN  1024
#define ENCN 256

// -------- tagged scratch: payload carries the ready-flag --------
__device__ float2 g_h1v[HID], g_h2v[HID], g_h1bv[HID], g_h2bv[HID];
__device__ float4 g_spec[BINS];            // {re, im, tag, pad}
__device__ float2 g_y1v[WIN];
__device__ float2 g_encv[ENCN];
__device__ float2 g_estv[ENCN];
__device__ unsigned g_epoch;               // bumped once per launch by CTA0

__device__ __forceinline__ float wsum(float v){
#pragma unroll
    for (int o = 16; o > 0; o >>= 1) v += __shfl_xor_sync(0xffffffffu, v, o);
    return v;
}
__device__ __forceinline__ float sigm(float x){ return 1.0f/(1.0f+__expf(-x)); }

__device__ __forceinline__ void stg_tag(float2* p, float v, unsigned tag){
    asm volatile("st.global.v2.b32 [%0], {%1,%2};" :: "l"(p),
                 "r"(__float_as_uint(v)), "r"(tag) : "memory");
}
__device__ __forceinline__ void stg_tag4(float4* p, float re, float im, unsigned tag){
    asm volatile("st.global.v4.b32 [%0], {%1,%2,%3,%4};" :: "l"(p),
                 "r"(__float_as_uint(re)), "r"(__float_as_uint(im)), "r"(tag), "r"(0u)
                 : "memory");
}
// Batched poll: N elements at p, p+32, p+64, ... (per-lane stride-32 layout).
template<int N>
__device__ __forceinline__ void pollN(const float2* p, float* dst, unsigned tag){
    unsigned vx[N], vy[N];
#pragma unroll
    for (int i = 0; i < N; i++) vy[i] = tag + 1u;
    bool bad = true;
    while (bad){
        bad = false;
#pragma unroll
        for (int i = 0; i < N; i++){
            if (vy[i] != tag){
                asm volatile("ld.volatile.global.v2.b32 {%0,%1}, [%2];"
                             : "=r"(vx[i]), "=r"(vy[i]) : "l"(p + i*32));
                if (vy[i] != tag) bad = true;
            }
        }
    }
#pragma unroll
    for (int i = 0; i < N; i++) dst[i] = __uint_as_float(vx[i]);
}
__device__ __forceinline__ float poll1(const float2* p, unsigned tag){
    unsigned vx, vy;
    do {
        asm volatile("ld.volatile.global.v2.b32 {%0,%1}, [%2];" : "=r"(vx), "=r"(vy) : "l"(p));
    } while (vy != tag);
    return __uint_as_float(vx);
}
__device__ __forceinline__ float2 poll_spec1(const float4* p, unsigned tag){
    unsigned a,b,c,d;
    do {
        asm volatile("ld.volatile.global.v4.b32 {%0,%1,%2,%3}, [%4];"
                     : "=r"(a), "=r"(b), "=r"(c), "=r"(d) : "l"(p));
    } while (c != tag);
    return make_float2(__uint_as_float(a), __uint_as_float(b));
}

template<int NX, int NXR>
__device__ __forceinline__ void lstm_preload(
    int j, int lane,
    const float* __restrict__ wih, const float* __restrict__ whh,
    const float* __restrict__ bih, const float* __restrict__ bhh,
    const float* __restrict__ hvec,
    float wi[4][17], float wh[4][4], float hr[4], float bsum[4])
{
#pragma unroll
    for (int g = 0; g < 4; g++){
        const float* w = wih + (size_t)(g*HID + j)*NX;
#pragma unroll
        for (int i = 0; i < NXR; i++){
            int k = lane + 32*i;
            wi[g][i] = ((NX & 31) == 0 || k < NX) ? w[k] : 0.f;
        }
        const float* whp = whh + (size_t)(g*HID + j)*HID;
#pragma unroll
        for (int i = 0; i < 4; i++) wh[g][i] = whp[lane + 32*i];
        bsum[g] = bih[g*HID + j] + bhh[g*HID + j];
    }
#pragma unroll
    for (int i = 0; i < 4; i++) hr[i] = hvec[lane + 32*i];
}

template<int NXR>
__device__ __forceinline__ void lstm_fire(
    int lane, const float wi[4][17], const float wh[4][4],
    const float* xr, const float hr[4], const float bsum[4],
    float cprev, float2* hdst, float* hout, float* cout, unsigned tag)
{
    float a[4];
#pragma unroll
    for (int g = 0; g < 4; g++){
        float acc = 0.f;
#pragma unroll
        for (int i = 0; i < NXR; i++) acc = fmaf(wi[g][i], xr[i], acc);
#pragma unroll
        for (int i = 0; i < 4; i++)   acc = fmaf(wh[g][i], hr[i], acc);
        a[g] = wsum(acc) + bsum[g];
    }
    if (lane == 0){
        float c2 = sigm(a[1])*cprev + sigm(a[0])*tanhf(a[2]);
        float h2 = sigm(a[3])*tanhf(c2);
        stg_tag(hdst, h2, tag);
        *hout = h2; *cout = c2;
    }
}

__device__ __forceinline__ int skew(int i){ return i + (i >> 5); }

__global__ void __launch_bounds__(NTHR) dtln_kernel(
    const float* __restrict__ mag,   const float* __restrict__ phase,
    const float* __restrict__ st1,   const float* __restrict__ st2,
    const float* __restrict__ wih10, const float* __restrict__ whh10,
    const float* __restrict__ bih10, const float* __restrict__ bhh10,
    const float* __restrict__ wih11, const float* __restrict__ whh11,
    const float* __restrict__ bih11, const float* __restrict__ bhh11,
    const float* __restrict__ d1w,   const float* __restrict__ d1b,
    const float* __restrict__ encw,  const float* __restrict__ gamma_,
    const float* __restrict__ beta_,
    const float* __restrict__ wih20, const float* __restrict__ whh20,
    const float* __restrict__ bih20, const float* __restrict__ bhh20,
    const float* __restrict__ wih21, const float* __restrict__ whh21,
    const float* __restrict__ bih21, const float* __restrict__ bhh21,
    const float* __restrict__ d2w,   const float* __restrict__ d2b,
    const float* __restrict__ decw,
    float* __restrict__ out)
{
    const int tid  = threadIdx.x;
    const int lane = tid & 31;
    const int wid  = tid >> 5;
    const int cta  = blockIdx.x;
    const int gw   = cta * 8 + wid;      // 0..1023

    const unsigned TAG = *((volatile unsigned*)&g_epoch) + 1u;

    __shared__ float2 s_tw[WIN + 32];
    __shared__ float  s_encn[ENCN];
    __shared__ float  s_red[8];

    float decr[8];
    if (cta >= 16){
        const float* wr = decw + (size_t)gw*ENCN;
#pragma unroll
        for (int i = 0; i < 8; i++) decr[i] = wr[lane + 32*i];
    }

    if (cta < 16){
        // ========== G1: LSTM1 layer0 ==========
        float wi[4][17], wh4[4][4], hr[4], bsum[4];
        int j = gw;
        lstm_preload<BINS,17>(j, lane, wih10, whh10, bih10, bhh10, st1, wi, wh4, hr, bsum);
        float cprev = st1[2*HID + j];
        float xr[17];
#pragma unroll
        for (int i = 0; i < 17; i++){ int k = lane + 32*i; xr[i] = (k < BINS) ? mag[k] : 0.f; }
        lstm_fire<17>(lane, wi, wh4, xr, hr, bsum, cprev,
                      &g_h1v[j], &out[WIN + j], &out[WIN + 2*HID + j], TAG);
        // deferred decoder-row preload (off critical path here)
        const float* wr = decw + (size_t)gw*ENCN;
#pragma unroll
        for (int i = 0; i < 8; i++) decr[i] = wr[lane + 32*i];
    }
    else if (cta < 32){
        // ========== G2: LSTM1 layer1 ==========
        float wi[4][17], wh4[4][4], hr[4], bsum[4];
        int j = gw - 128;
        lstm_preload<HID,4>(j, lane, wih11, whh11, bih11, bhh11, st1 + HID, wi, wh4, hr, bsum);
        float cprev = st1[3*HID + j];
        float xr[4];
        pollN<4>(g_h1v + lane, xr, TAG);
        lstm_fire<4>(lane, wi, wh4, xr, hr, bsum, cprev,
                     &g_h2v[j], &out[WIN + HID + j], &out[WIN + 3*HID + j], TAG);
    }
    else if (cta < 64){
        // ========== G3: dense1 -> spectrum, then LSTM2a (32-47) / LSTM2b (48-63) ==========
        int dw = gw - 256;                 // 0..255
        int r0 = dw, r1 = dw + 256;
        float w0[4], w1[4], w2[4];
        float b0, b1, b2 = 0.f, m0, m1, m2 = 0.f;
        float c0, s0, c1, s1, c2v = 1.f, s2v = 0.f;
        {
            const float* wr0 = d1w + (size_t)r0*HID;
            const float* wr1 = d1w + (size_t)r1*HID;
#pragma unroll
            for (int i = 0; i < 4; i++){ w0[i] = wr0[lane+32*i]; w1[i] = wr1[lane+32*i]; }
            b0 = d1b[r0]; b1 = d1b[r1];
            m0 = mag[r0]; m1 = mag[r1];
            sincosf(phase[r0], &s0, &c0);
            sincosf(phase[r1], &s1, &c1);
            if (dw == 0){
                const float* wr2 = d1w + (size_t)512*HID;
#pragma unroll
                for (int i = 0; i < 4; i++) w2[i] = wr2[lane+32*i];
                b2 = d1b[512]; m2 = mag[512];
                sincosf(phase[512], &s2v, &c2v);
            }
        }
        float wi[4][17], wh4[4][4], hr[4], bsum[4], cprev;
        float gam = 0.f, bet = 0.f;
        if (cta < 48){
            int j = gw - 256;
            lstm_preload<ENCN,8>(j, lane, wih20, whh20, bih20, bhh20, st2, wi, wh4, hr, bsum);
            cprev = st2[2*HID + j];
            gam = gamma_[tid]; bet = beta_[tid];
        } else {
            int j = gw - 384;
            lstm_preload<HID,4>(j, lane, wih21, whh21, bih21, bhh21, st2 + HID, wi, wh4, hr, bsum);
            cprev = st2[3*HID + j];
        }

        {
            float xr[4];
            pollN<4>(g_h2v + lane, xr, TAG);
            float a0 = 0.f, a1 = 0.f, a2 = 0.f;
#pragma unroll
            for (int i = 0; i < 4; i++){
                a0 = fmaf(w0[i], xr[i], a0);
                a1 = fmaf(w1[i], xr[i], a1);
                a2 = fmaf((dw==0)?w2[i]:0.f, xr[i], a2);
            }
            a0 = wsum(a0); a1 = wsum(a1); a2 = wsum(a2);
            if (lane == 0){
                float e0 = sigm(a0 + b0) * m0;
                float e1 = sigm(a1 + b1) * m1;
                stg_tag4(&g_spec[r0], e0*c0, e0*s0, TAG);
                stg_tag4(&g_spec[r1], e1*c1, e1*s1, TAG);
                if (dw == 0){
                    float e2 = sigm(a2 + b2) * m2;
                    stg_tag4(&g_spec[512], e2*c2v, e2*s2v, TAG);
                }
            }
        }

        if (cta < 48){
            // ---- instance norm + LSTM2 layer0 ----
            float v = poll1(&g_encv[tid], TAG);
            float t1 = wsum(v);
            if (lane == 0) s_red[wid] = t1;
            __syncthreads();
            float tot = 0.f;
#pragma unroll
            for (int i = 0; i < 8; i++) tot += s_red[i];
            float mean = tot * (1.0f/ENCN);
            float d = v - mean;
            float t2 = wsum(d*d);
            __syncthreads();
            if (lane == 0) s_red[wid] = t2;
            __syncthreads();
            float tot2 = 0.f;
#pragma unroll
            for (int i = 0; i < 8; i++) tot2 += s_red[i];
            float rstd = rsqrtf(tot2 * (1.0f/ENCN) + 1e-7f);
            s_encn[tid] = d * rstd * gam + bet;
            __syncthreads();

            int j = gw - 256;
            float xr[8];
#pragma unroll
            for (int i = 0; i < 8; i++) xr[i] = s_encn[lane + 32*i];
            lstm_fire<8>(lane, wi, wh4, xr, hr, bsum, cprev,
                         &g_h1bv[j], &out[WIN + 4*HID + j], &out[WIN + 6*HID + j], TAG);
        } else {
            // ---- LSTM2 layer1 ----
            int j = gw - 384;
            float xr[4];
            pollN<4>(g_h1bv + lane, xr, TAG);
            lstm_fire<4>(lane, wi, wh4, xr, hr, bsum, cprev,
                         &g_h2bv[j], &out[WIN + 5*HID + j], &out[WIN + 7*HID + j], TAG);
        }
    }
    else if (cta < 96){
        // ========== G4: iDFT then encoder ==========
        int w = gw - 512;                 // 0..255
        float wrow[32];
        {
            const float* wr = encw + (size_t)w*WIN;
#pragma unroll
            for (int i = 0; i < 32; i++) wrow[i] = wr[lane + 32*i];
        }
        for (int i = tid; i < WIN; i += NTHR){
            float s, c; sincospif((float)i * (1.0f/512.0f), &s, &c);
            s_tw[skew(i)] = make_float2(c, s);
        }
        __syncthreads();

        // iDFT: warp computes y1[n0..n0+3]
        int n0 = w * 4;
        float acc[4] = {0.f,0.f,0.f,0.f};
        float nyqv = 0.f;
        float sr0l = 0.f;
        if (lane == 0){ float2 z = poll_spec1(&g_spec[0], TAG); sr0l = z.x; }
#pragma unroll
        for (int h = 0; h < 2; h++){
            unsigned ax[8], ay[8], az[8], aw;
#pragma unroll
            for (int t = 0; t < 8; t++) az[t] = TAG + 1u;
            bool bad = true;
            while (bad){
                bad = false;
#pragma unroll
                for (int t = 0; t < 8; t++){
                    if (az[t] != TAG){
                        const float4* p = &g_spec[1 + lane + 32*(8*h + t)];
                        asm volatile("ld.volatile.global.v4.b32 {%0,%1,%2,%3}, [%4];"
                                     : "=r"(ax[t]), "=r"(ay[t]), "=r"(az[t]), "=r"(aw)
                                     : "l"(p));
                        if (az[t] != TAG) bad = true;
                    }
                }
            }
#pragma unroll
            for (int t = 0; t < 8; t++){
                int k = 1 + lane + 32*(8*h + t);
                float sr = __uint_as_float(ax[t]);
                float si = __uint_as_float(ay[t]);
                if (k < 512){
                    int base = (k * n0) & (WIN-1);
#pragma unroll
                    for (int q = 0; q < 4; q++){
                        int idx = (base + q*k) & (WIN-1);
                        float2 cs = s_tw[skew(idx)];
                        acc[q] += sr*cs.x - si*cs.y;
                    }
                } else {
                    nyqv = sr;           // k == 512 (only lane 31, h=1, t=7)
                }
            }
        }
        float nyq = __shfl_sync(0xffffffffu, nyqv, 31);
        float sr0 = __shfl_sync(0xffffffffu, sr0l, 0);
#pragma unroll
        for (int q = 0; q < 4; q++){
            float a = wsum(acc[q]);
            if (lane == 0){
                int n = n0 + q;
                float ny = (n & 1) ? -nyq : nyq;
                stg_tag(&g_y1v[n], (sr0 + 2.0f*a + ny) * (1.0f/1024.0f), TAG);
            }
        }

        // encoder row w: chunked poll of y1
        float eacc = 0.f;
#pragma unroll
        for (int q = 0; q < 4; q++){
            float yv[8];
            pollN<8>(g_y1v + 256*q + lane, yv, TAG);
#pragma unroll
            for (int i = 0; i < 8; i++) eacc = fmaf(wrow[8*q + i], yv[i], eacc);
        }
        eacc = wsum(eacc);
        if (lane == 0) stg_tag(&g_encv[w], eacc, TAG);
    }
    else {
        // ========== G6: dense2 -> est ==========
        int r = gw - 768;                 // 0..255
        float d2r[4];
        {
            const float* wr = d2w + (size_t)r*HID;
#pragma unroll
            for (int i = 0; i < 4; i++) d2r[i] = wr[lane + 32*i];
        }
        float d2bias = d2b[r];
        float xr[4];
        pollN<4>(g_h2bv + lane, xr, TAG);
        float acc = 0.f;
#pragma unroll
        for (int i = 0; i < 4; i++) acc = fmaf(d2r[i], xr[i], acc);
        acc = wsum(acc);
        if (lane == 0){
            float encv = poll1(&g_encv[r], TAG);
            stg_tag(&g_estv[r], sigm(acc + d2bias) * encv, TAG);
        }
    }

    // ========== decoder (all warps): out[gw] = decw[gw] . est ==========
    {
        float xr[8];
        pollN<8>(g_estv + lane, xr, TAG);
        float acc = 0.f;
#pragma unroll
        for (int i = 0; i < 8; i++) acc = fmaf(decr[i], xr[i], acc);
        acc = wsum(acc);
        if (lane == 0) out[gw] = acc;
    }

    // epoch bump: CTA0 exits last-enough; next launch is stream-ordered anyway.
    if (cta == 0 && tid == 0) g_epoch = TAG;
}

extern "C" void kernel_launch(void* const* d_in, const int* in_sizes, int n_in,
                              void* d_out, int out_size)
{
    (void)in_sizes; (void)n_in; (void)out_size;
    dtln_kernel<<<NBLK, NTHR>>>(
        (const float*)d_in[0],  (const float*)d_in[1],
        (const float*)d_in[2],  (const float*)d_in[3],
        (const float*)d_in[4],  (const float*)d_in[5],
        (const float*)d_in[6],  (const float*)d_in[7],
        (const float*)d_in[8],  (const float*)d_in[9],
        (const float*)d_in[10], (const float*)d_in[11],
        (const float*)d_in[12], (const float*)d_in[13],
        (const float*)d_in[14], (const float*)d_in[15],
        (const float*)d_in[16],
        (const float*)d_in[17], (const float*)d_in[18],
        (const float*)d_in[19], (const float*)d_in[20],
        (const float*)d_in[21], (const float*)d_in[22],
        (const float*)d_in[23], (const float*)d_in[24],
        (const float*)d_in[25], (const float*)d_in[26],
        (const float*)d_in[27],
        (float*)d_out);
}

// round 5
// speedup vs baseline: 1.1120x; 1.1120x over previous
#include <cuda_runtime.h>
#include <math.h>

#define NCTA 8
#define NTHR 512
#define HID  128
#define BINS 513
#define WIN  1024
#define ENCN 256

__device__ __forceinline__ float wsum(float v){
#pragma unroll
    for (int o = 16; o > 0; o >>= 1) v += __shfl_xor_sync(0xffffffffu, v, o);
    return v;
}
__device__ __forceinline__ float sigm(float x){ return 1.0f/(1.0f+__expf(-x)); }

__device__ __forceinline__ unsigned su32(const void* p){
    unsigned a;
    asm("{ .reg .u64 t; cvta.to.shared.u64 t, %1; cvt.u32.u64 %0, t; }" : "=r"(a) : "l"(p));
    return a;
}
// Atomic 8B {value, tag=1} push into rank's smem mirror at the same offset.
__device__ __forceinline__ void push(unsigned laddr, float v, unsigned rank){
    unsigned ra;
    asm volatile("mapa.shared::cluster.u32 %0, %1, %2;" : "=r"(ra) : "r"(laddr), "r"(rank));
    unsigned long long pk = (unsigned long long)__float_as_uint(v) | (1ull << 32);
    asm volatile("st.shared::cluster.u64 [%0], %1;" :: "r"(ra), "l"(pk) : "memory");
}
// Poll N tagged entries at addr + i*stride (bytes) from LOCAL smem.
template<int N>
__device__ __forceinline__ void pollT(unsigned addr, int stride, float* dst){
    bool done[N];
#pragma unroll
    for (int i = 0; i < N; i++) done[i] = false;
    for (;;){
        bool bad = false;
#pragma unroll
        for (int i = 0; i < N; i++){
            if (!done[i]){
                unsigned long long u;
                asm volatile("ld.volatile.shared.u64 %0, [%1];" : "=l"(u)
                             : "r"(addr + (unsigned)(i*stride)));
                if ((unsigned)(u >> 32) == 1u){ dst[i] = __uint_as_float((unsigned)u); done[i] = true; }
                else bad = true;
            }
        }
        if (!__any_sync(0xffffffffu, bad)) break;
    }
}
__device__ __forceinline__ float poll1u(unsigned addr){
    unsigned long long u;
    do { asm volatile("ld.volatile.shared.u64 %0, [%1];" : "=l"(u) : "r"(addr)); }
    while ((unsigned)(u >> 32) != 1u);
    return __uint_as_float((unsigned)u);
}

struct __align__(16) Smem {
    float2 h1[HID];            // tagged
    float2 h2[HID];
    float2 h1b[HID];
    float2 h2b[HID];
    float2 sr[BINS];
    float2 si[BINS];
    float2 y1[WIN];
    float2 enc[ENCN];
    float2 est[ENCN];         // tagged region ends here (3074 float2)
    float2 tw[WIN + 32];
    float  encn[ENCN];
    float  red[16];
    float  red2[16];
};
#define NTAGGED 3074

__global__ void __launch_bounds__(NTHR, 1) __cluster_dims__(NCTA, 1, 1)
dtln_kernel(
    const float* __restrict__ mag,   const float* __restrict__ phase,
    const float* __restrict__ st1,   const float* __restrict__ st2,
    const float* __restrict__ wih10, const float* __restrict__ whh10,
    const float* __restrict__ bih10, const float* __restrict__ bhh10,
    const float* __restrict__ wih11, const float* __restrict__ whh11,
    const float* __restrict__ bih11, const float* __restrict__ bhh11,
    const float* __restrict__ d1w,   const float* __restrict__ d1b,
    const float* __restrict__ encw,  const float* __restrict__ gamma_,
    const float* __restrict__ beta_,
    const float* __restrict__ wih20, const float* __restrict__ whh20,
    const float* __restrict__ bih20, const float* __restrict__ bhh20,
    const float* __restrict__ wih21, const float* __restrict__ whh21,
    const float* __restrict__ bih21, const float* __restrict__ bhh21,
    const float* __restrict__ d2w,   const float* __restrict__ d2b,
    const float* __restrict__ decw,
    float* __restrict__ out)
{
    __shared__ Smem sm;
    const int tid  = threadIdx.x;
    const int lane = tid & 31;
    const int wid  = tid >> 5;
    const int cta  = blockIdx.x;          // == cluster rank (grid == cluster)
    const int gw   = cta * 16 + wid;      // global warp id 0..127

    const unsigned a_h1  = su32(sm.h1);
    const unsigned a_h2  = su32(sm.h2);
    const unsigned a_h1b = su32(sm.h1b);
    const unsigned a_h2b = su32(sm.h2b);
    const unsigned a_sr  = su32(sm.sr);
    const unsigned a_si  = su32(sm.si);
    const unsigned a_y1  = su32(sm.y1);
    const unsigned a_enc = su32(sm.enc);
    const unsigned a_est = su32(sm.est);

    // ---- entry: zero tags, build twiddle, intra-CTA sync, cluster arrive ----
    {
        float2* z = (float2*)&sm;
        for (int i = tid; i < NTAGGED; i += NTHR) z[i] = make_float2(0.f, 0.f);
        for (int m = tid; m < WIN; m += NTHR){
            float s, c; sincospif((float)m * (1.0f/512.0f), &s, &c);
            sm.tw[m + (m >> 5)] = make_float2(c, s);
        }
    }
    __syncthreads();
    asm volatile("barrier.cluster.arrive.aligned;" ::: "memory");

    // ---- S1 weight/input loads (hidden under cluster wait) ----
    float wiA[4][17], whA[4][4], bA[4], hrA[4], xrA[17], cprevA;
    {
#pragma unroll
        for (int g = 0; g < 4; g++){
            const float* w = wih10 + (size_t)(g*HID + gw)*BINS;
#pragma unroll
            for (int i = 0; i < 17; i++){ int k = lane + 32*i; wiA[g][i] = (k < BINS) ? w[k] : 0.f; }
            const float* wh = whh10 + (size_t)(g*HID + gw)*HID;
#pragma unroll
            for (int i = 0; i < 4; i++) whA[g][i] = wh[lane + 32*i];
            bA[g] = bih10[g*HID + gw] + bhh10[g*HID + gw];
        }
#pragma unroll
        for (int i = 0; i < 17; i++){ int k = lane + 32*i; xrA[i] = (k < BINS) ? mag[k] : 0.f; }
#pragma unroll
        for (int i = 0; i < 4; i++) hrA[i] = st1[lane + 32*i];
        cprevA = st1[2*HID + gw];
    }
    asm volatile("barrier.cluster.wait.aligned;" ::: "memory");

    // ================= S1: LSTM1 layer0 (unit gw) =================
    {
        float a[4];
#pragma unroll
        for (int g = 0; g < 4; g++){
            float acc = 0.f;
#pragma unroll
            for (int i = 0; i < 17; i++) acc = fmaf(wiA[g][i], xrA[i], acc);
#pragma unroll
            for (int i = 0; i < 4; i++)  acc = fmaf(whA[g][i], hrA[i], acc);
            a[g] = wsum(acc) + bA[g];
        }
        float c2 = sigm(a[1])*cprevA + sigm(a[0])*tanhf(a[2]);
        float h2 = sigm(a[3])*tanhf(c2);
        if (lane == 0){ out[WIN + gw] = h2; out[WIN + 2*HID + gw] = c2; }
        if (lane < NCTA) push(a_h1 + gw*8, h2, lane);
    }

    // ================= S2: LSTM1 layer1 (unit gw) =================
    {
        float4 wiB[4], whB[4]; float bB[4];
#pragma unroll
        for (int g = 0; g < 4; g++){
            wiB[g] = *(const float4*)(wih11 + (size_t)(g*HID + gw)*HID + lane*4);
            whB[g] = *(const float4*)(whh11 + (size_t)(g*HID + gw)*HID + lane*4);
            bB[g]  = bih11[g*HID + gw] + bhh11[g*HID + gw];
        }
        float4 hrB = *(const float4*)(st1 + HID + lane*4);
        float cprevB = st1[3*HID + gw];
        float xB[4];
        pollT<4>(a_h1 + lane*4*8, 8, xB);
        float a[4];
#pragma unroll
        for (int g = 0; g < 4; g++){
            float acc = wiB[g].x*xB[0] + wiB[g].y*xB[1] + wiB[g].z*xB[2] + wiB[g].w*xB[3]
                      + whB[g].x*hrB.x + whB[g].y*hrB.y + whB[g].z*hrB.z + whB[g].w*hrB.w;
            a[g] = wsum(acc) + bB[g];
        }
        float c2 = sigm(a[1])*cprevB + sigm(a[0])*tanhf(a[2]);
        float h2 = sigm(a[3])*tanhf(c2);
        if (lane == 0){ out[WIN + HID + gw] = h2; out[WIN + 3*HID + gw] = c2; }
        if (lane < NCTA) push(a_h2 + gw*8, h2, lane);
    }

    // ================= S3: dense1 -> complex spectrum (rows gw*4..+3, +512) =================
    {
        int r0 = gw*4;
        float4 wD0 = *(const float4*)(d1w + (size_t)(r0+0)*HID + lane*4);
        float4 wD1 = *(const float4*)(d1w + (size_t)(r0+1)*HID + lane*4);
        float4 wD2 = *(const float4*)(d1w + (size_t)(r0+2)*HID + lane*4);
        float4 wD3 = *(const float4*)(d1w + (size_t)(r0+3)*HID + lane*4);
        float b0 = d1b[r0+0], b1 = d1b[r0+1], b2 = d1b[r0+2], b3 = d1b[r0+3];
        float m0 = mag[r0+0], m1 = mag[r0+1], m2 = mag[r0+2], m3 = mag[r0+3];
        float c0,s0,c1,s1,c2,s2,c3,s3;
        sincosf(phase[r0+0], &s0, &c0);  sincosf(phase[r0+1], &s1, &c1);
        sincosf(phase[r0+2], &s2, &c2);  sincosf(phase[r0+3], &s3, &c3);
        float4 w512; float b5=0.f, m5=0.f, c5=1.f, s5=0.f;
        if (gw == 127){
            w512 = *(const float4*)(d1w + (size_t)512*HID + lane*4);
            b5 = d1b[512]; m5 = mag[512];
            sincosf(phase[512], &s5, &c5);
        }
        float x[4];
        pollT<4>(a_h2 + lane*4*8, 8, x);
        float a0 = wsum(wD0.x*x[0]+wD0.y*x[1]+wD0.z*x[2]+wD0.w*x[3]) + b0;
        float a1 = wsum(wD1.x*x[0]+wD1.y*x[1]+wD1.z*x[2]+wD1.w*x[3]) + b1;
        float a2 = wsum(wD2.x*x[0]+wD2.y*x[1]+wD2.z*x[2]+wD2.w*x[3]) + b2;
        float a3 = wsum(wD3.x*x[0]+wD3.y*x[1]+wD3.z*x[2]+wD3.w*x[3]) + b3;
        float e0 = sigm(a0)*m0, e1 = sigm(a1)*m1, e2 = sigm(a2)*m2, e3 = sigm(a3)*m3;
        float re0=e0*c0, im0=e0*s0, re1=e1*c1, im1=e1*s1;
        float re2=e2*c2, im2=e2*s2, re3=e3*c3, im3=e3*s3;
        // 64 pushes: id = lane, lane+32 ; row=id>>4, comp=(id>>3)&1, rank=id&7
#pragma unroll
        for (int half = 0; half < 2; half++){
            int id   = lane + 32*half;
            int row  = id >> 4;
            int comp = (id >> 3) & 1;
            int rank = id & 7;
            float rv = (row == 0) ? re0 : ((row == 1) ? re1 : ((row == 2) ? re2 : re3));
            float iv = (row == 0) ? im0 : ((row == 1) ? im1 : ((row == 2) ? im2 : im3));
            float v  = comp ? iv : rv;
            unsigned base = comp ? a_si : a_sr;
            push(base + (unsigned)(r0 + row)*8, v, (unsigned)rank);
        }
        if (gw == 127){
            float a5 = wsum(w512.x*x[0]+w512.y*x[1]+w512.z*x[2]+w512.w*x[3]) + b5;
            float e5 = sigm(a5)*m5;
            float re5 = e5*c5, im5 = e5*s5;
            if (lane < 16){
                int comp = lane >> 3, rank = lane & 7;
                push((comp ? a_si : a_sr) + 512u*8u, comp ? im5 : re5, (unsigned)rank);
            }
        }
    }

    // ================= S4: iDFT (outputs gw*8..+7) — prefetch S5 weights first ============
    float4 wE[2][8];
    const int e0 = gw*2;
    {
#pragma unroll
        for (int rr = 0; rr < 2; rr++)
#pragma unroll
            for (int c = 0; c < 8; c++)
                wE[rr][c] = *(const float4*)(encw + (size_t)(e0+rr)*WIN + c*128 + lane*4);
    }
    {
        float srv[16], siv[16];
        pollT<16>(a_sr + (1+lane)*8, 32*8, srv);
        pollT<16>(a_si + (1+lane)*8, 32*8, siv);
        float dc  = poll1u(a_sr);
        float nyq = poll1u(a_sr + 512u*8u);
        __syncwarp();
        int n0 = gw*8;
        float acc[8] = {0.f,0.f,0.f,0.f,0.f,0.f,0.f,0.f};
#pragma unroll
        for (int t = 0; t < 16; t++){
            int k = 1 + lane + 32*t;
            if (k < 512){
                int base = (k * n0) & (WIN-1);
                float sr_ = srv[t], si_ = siv[t];
#pragma unroll
                for (int q = 0; q < 8; q++){
                    int idx = (base + q*k) & (WIN-1);
                    float2 cs = sm.tw[idx + (idx >> 5)];
                    acc[q] = fmaf(sr_, cs.x, acc[q]);
                    acc[q] = fmaf(-si_, cs.y, acc[q]);
                }
            }
        }
        float y0=0,y1v=0,y2=0,y3=0,y4=0,y5=0,y6=0,y7=0;
#pragma unroll
        for (int q = 0; q < 8; q++){
            float a = wsum(acc[q]);
            int n = n0 + q;
            float ny = (n & 1) ? -nyq : nyq;
            float yv = (dc + 2.0f*a + ny) * (1.0f/1024.0f);
            if (q==0) y0=yv; else if (q==1) y1v=yv; else if (q==2) y2=yv; else if (q==3) y3=yv;
            else if (q==4) y4=yv; else if (q==5) y5=yv; else if (q==6) y6=yv; else y7=yv;
        }
        // 64 pushes: id = lane, lane+32 ; q=id>>3, rank=id&7
#pragma unroll
        for (int half = 0; half < 2; half++){
            int id = lane + 32*half;
            int q  = id >> 3;
            int rank = id & 7;
            float v = (q < 4) ? ((q < 2) ? (q ? y1v : y0) : (q == 2 ? y2 : y3))
                              : ((q < 6) ? (q == 4 ? y4 : y5) : (q == 6 ? y6 : y7));
            push(a_y1 + (unsigned)(n0 + q)*8, v, (unsigned)rank);
        }
    }

    // ================= S5: encoder rows e0, e0+1 =================
    {
        float yf[32];
        unsigned miss = 0xffffffffu;
        for (;;){
            bool bad = false;
#pragma unroll
            for (int c = 0; c < 8; c++)
#pragma unroll
                for (int i = 0; i < 4; i++){
                    int t = c*4 + i;
                    if (miss & (1u << t)){
                        unsigned long long u;
                        unsigned ad = a_y1 + (unsigned)((c*128 + lane*4 + i)*8);
                        asm volatile("ld.volatile.shared.u64 %0, [%1];" : "=l"(u) : "r"(ad));
                        if ((unsigned)(u >> 32) == 1u){ yf[t] = __uint_as_float((unsigned)u); miss &= ~(1u << t); }
                        else bad = true;
                    }
                }
            if (!__any_sync(0xffffffffu, bad)) break;
        }
        float ea = 0.f, eb = 0.f;
#pragma unroll
        for (int c = 0; c < 8; c++){
            ea = fmaf(wE[0][c].x, yf[c*4+0], ea); ea = fmaf(wE[0][c].y, yf[c*4+1], ea);
            ea = fmaf(wE[0][c].z, yf[c*4+2], ea); ea = fmaf(wE[0][c].w, yf[c*4+3], ea);
            eb = fmaf(wE[1][c].x, yf[c*4+0], eb); eb = fmaf(wE[1][c].y, yf[c*4+1], eb);
            eb = fmaf(wE[1][c].z, yf[c*4+2], eb); eb = fmaf(wE[1][c].w, yf[c*4+3], eb);
        }
        ea = wsum(ea); eb = wsum(eb);
        if (lane < 16){
            int rr = lane >> 3, rank = lane & 7;
            push(a_enc + (unsigned)(e0 + rr)*8, rr ? eb : ea, (unsigned)rank);
        }
    }

    // ================= S6: instance norm + LSTM2 layer0 (unit gw) =================
    {
        float4 wiC0[4], wiC1[4], whC[4]; float bC[4];
#pragma unroll
        for (int g = 0; g < 4; g++){
            wiC0[g] = *(const float4*)(wih20 + (size_t)(g*HID + gw)*ENCN + lane*8);
            wiC1[g] = *(const float4*)(wih20 + (size_t)(g*HID + gw)*ENCN + lane*8 + 4);
            whC[g]  = *(const float4*)(whh20 + (size_t)(g*HID + gw)*HID + lane*4);
            bC[g]   = bih20[g*HID + gw] + bhh20[g*HID + gw];
        }
        float4 hrC = *(const float4*)(st2 + lane*4);
        float cprevC = st2[2*HID + gw];
        float gamv = 0.f, betv = 0.f;
        if (tid < ENCN){ gamv = gamma_[tid]; betv = beta_[tid]; }

        float v = 0.f;
        if (tid < ENCN) v = poll1u(a_enc + (unsigned)tid*8);
        __syncwarp();
        float t1 = wsum(v);
        if (lane == 0) sm.red[wid] = t1;
        __syncthreads();
        float tot = 0.f;
#pragma unroll
        for (int i = 0; i < 16; i++) tot += sm.red[i];
        float mean = tot * (1.0f/ENCN);
        float d = (tid < ENCN) ? (v - mean) : 0.f;
        float t2 = wsum(d*d);
        if (lane == 0) sm.red2[wid] = t2;
        __syncthreads();
        float tot2 = 0.f;
#pragma unroll
        for (int i = 0; i < 16; i++) tot2 += sm.red2[i];
        float rstd = rsqrtf(tot2 * (1.0f/ENCN) + 1e-7f);
        if (tid < ENCN) sm.encn[tid] = d * rstd * gamv + betv;
        __syncthreads();

        float4 x0 = *(const float4*)&sm.encn[lane*8];
        float4 x1 = *(const float4*)&sm.encn[lane*8 + 4];
        float a[4];
#pragma unroll
        for (int g = 0; g < 4; g++){
            float acc = wiC0[g].x*x0.x + wiC0[g].y*x0.y + wiC0[g].z*x0.z + wiC0[g].w*x0.w
                      + wiC1[g].x*x1.x + wiC1[g].y*x1.y + wiC1[g].z*x1.z + wiC1[g].w*x1.w
                      + whC[g].x*hrC.x + whC[g].y*hrC.y + whC[g].z*hrC.z + whC[g].w*hrC.w;
            a[g] = wsum(acc) + bC[g];
        }
        float c2 = sigm(a[1])*cprevC + sigm(a[0])*tanhf(a[2]);
        float h2 = sigm(a[3])*tanhf(c2);
        if (lane == 0){ out[WIN + 4*HID + gw] = h2; out[WIN + 6*HID + gw] = c2; }
        if (lane < NCTA) push(a_h1b + gw*8, h2, lane);
    }

    // ================= S7: LSTM2 layer1 (unit gw) =================
    {
        float4 wiB[4], whB[4]; float bB[4];
#pragma unroll
        for (int g = 0; g < 4; g++){
            wiB[g] = *(const float4*)(wih21 + (size_t)(g*HID + gw)*HID + lane*4);
            whB[g] = *(const float4*)(whh21 + (size_t)(g*HID + gw)*HID + lane*4);
            bB[g]  = bih21[g*HID + gw] + bhh21[g*HID + gw];
        }
        float4 hrB = *(const float4*)(st2 + HID + lane*4);
        float cprevB = st2[3*HID + gw];
        float xB[4];
        pollT<4>(a_h1b + lane*4*8, 8, xB);
        float a[4];
#pragma unroll
        for (int g = 0; g < 4; g++){
            float acc = wiB[g].x*xB[0] + wiB[g].y*xB[1] + wiB[g].z*xB[2] + wiB[g].w*xB[3]
                      + whB[g].x*hrB.x + whB[g].y*hrB.y + whB[g].z*hrB.z + whB[g].w*hrB.w;
            a[g] = wsum(acc) + bB[g];
        }
        float c2 = sigm(a[1])*cprevB + sigm(a[0])*tanhf(a[2]);
        float h2 = sigm(a[3])*tanhf(c2);
        if (lane == 0){ out[WIN + 5*HID + gw] = h2; out[WIN + 7*HID + gw] = c2; }
        if (lane < NCTA) push(a_h2b + gw*8, h2, lane);
    }

    // ================= S8: dense2 -> est (rows gw*2, +1) =================
    {
        int r2 = gw*2;
        float4 wF0 = *(const float4*)(d2w + (size_t)(r2+0)*HID + lane*4);
        float4 wF1 = *(const float4*)(d2w + (size_t)(r2+1)*HID + lane*4);
        float bF0 = d2b[r2+0], bF1 = d2b[r2+1];
        float ev0 = sm.enc[r2+0].x, ev1 = sm.enc[r2+1].x;   // complete since S6 sync
        float x[4];
        pollT<4>(a_h2b + lane*4*8, 8, x);
        float a0 = wsum(wF0.x*x[0]+wF0.y*x[1]+wF0.z*x[2]+wF0.w*x[3]) + bF0;
        float a1 = wsum(wF1.x*x[0]+wF1.y*x[1]+wF1.z*x[2]+wF1.w*x[3]) + bF1;
        float es0 = sigm(a0)*ev0, es1 = sigm(a1)*ev1;
        if (lane < 16){
            int rr = lane >> 3, rank = lane & 7;
            push(a_est + (unsigned)(r2 + rr)*8, rr ? es1 : es0, (unsigned)rank);
        }
    }

    // ================= S9: decoder rows gw*8..+7 =================
    {
        int n0 = gw*8;
        float4 wD[8][2];
#pragma unroll
        for (int q = 0; q < 8; q++){
            wD[q][0] = *(const float4*)(decw + (size_t)(n0+q)*ENCN + lane*8);
            wD[q][1] = *(const float4*)(decw + (size_t)(n0+q)*ENCN + lane*8 + 4);
        }
        float er[8];
        pollT<8>(a_est + lane*8*8, 8, er);
#pragma unroll
        for (int q = 0; q < 8; q++){
            float acc = wD[q][0].x*er[0] + wD[q][0].y*er[1] + wD[q][0].z*er[2] + wD[q][0].w*er[3]
                      + wD[q][1].x*er[4] + wD[q][1].y*er[5] + wD[q][1].z*er[6] + wD[q][1].w*er[7];
            acc = wsum(acc);
            if (lane == 0) out[n0 + q] = acc;
        }
    }
}

extern "C" void kernel_launch(void* const* d_in, const int* in_sizes, int n_in,
                              void* d_out, int out_size)
{
    (void)in_sizes; (void)n_in; (void)out_size;
    dtln_kernel<<<NCTA, NTHR>>>(
        (const float*)d_in[0],  (const float*)d_in[1],
        (const float*)d_in[2],  (const float*)d_in[3],
        (const float*)d_in[4],  (const float*)d_in[5],
        (const float*)d_in[6],  (const float*)d_in[7],
        (const float*)d_in[8],  (const float*)d_in[9],
        (const float*)d_in[10], (const float*)d_in[11],
        (const float*)d_in[12], (const float*)d_in[13],
        (const float*)d_in[14], (const float*)d_in[15],
        (const float*)d_in[16],
        (const float*)d_in[17], (const float*)d_in[18],
        (const float*)d_in[19], (const float*)d_in[20],
        (const float*)d_in[21], (const float*)d_in[22],
        (const float*)d_in[23], (const float*)d_in[24],
        (const float*)d_in[25], (const float*)d_in[26],
        (const float*)d_in[27],
        (float*)d_out);
}